// round 1
// baseline (speedup 1.0000x reference)
#include <cuda_runtime.h>
#include <cuda_bf16.h>

// out[e*12 + 0..11] = W[h=0..11][rel_pos[e]]  (gather of W^T rows)
// One thread per OUTPUT float4: gid -> element e = gid/3, chunk c = gid%3.
// Writes are perfectly contiguous/coalesced float4 across each warp.

__global__ __launch_bounds__(256)
void gather_wt_kernel(const int* __restrict__ rel_pos,
                      const float* __restrict__ W,      // [12, 64] row-major
                      float4* __restrict__ out4,
                      unsigned int n4)                   // total float4 count = n_elem*3
{
    // Transposed table in smem: table[c][h] = W[h*64 + c], 64 rows x 12 floats,
    // viewed as float4 so each row is 3 aligned float4s.
    __shared__ float4 table4[64 * 3];
    float* table = reinterpret_cast<float*>(table4);

    unsigned int t = threadIdx.x;
    #pragma unroll
    for (int i = 0; i < 3; i++) {
        unsigned int j = t + i * 256u;       // j in [0, 768)
        unsigned int h = j >> 6;             // j / 64
        unsigned int c = j & 63u;            // j % 64
        table[c * 12u + h] = W[j];
    }
    __syncthreads();

    unsigned int gid = blockIdx.x * 256u + t;
    if (gid < n4) {
        unsigned int e = gid / 3u;           // element index (compiler -> mul-shift)
        unsigned int c = gid - e * 3u;       // chunk 0..2
        int cls = rel_pos[e];                // 3 adjacent lanes share this load (L1 broadcast)
        out4[gid] = table4[(unsigned int)cls * 3u + c];
    }
}

extern "C" void kernel_launch(void* const* d_in, const int* in_sizes, int n_in,
                              void* d_out, int out_size)
{
    const int*   rel_pos = (const int*)d_in[0];    // [4,2048,2048] int32
    // d_in[1] = hidden_states (unused; only sets output dtype = float32)
    const float* W       = (const float*)d_in[2];  // [12,64] float32
    float4*      out4    = (float4*)d_out;

    unsigned int n_elem = (unsigned int)in_sizes[0];       // 16,777,216
    unsigned int n4     = n_elem * 3u;                     // 50,331,648 float4s
    unsigned int blocks = (n4 + 255u) / 256u;              // 196,608

    gather_wt_kernel<<<blocks, 256>>>(rel_pos, W, out4, n4);
}

// round 2
// speedup vs baseline: 1.4312x; 1.4312x over previous
#include <cuda_runtime.h>
#include <cuda_bf16.h>
#include <cstdint>

// out[e*12 + 0..11] = W[h][rel_pos[e]]  -> pure gather of W^T rows.
// R2: gather into a linear smem staging tile (conflict-free STS.128), then
// drain 16KB per block with one cp.async.bulk store (bypasses the per-element
// STG LSU/L1 path that dominated R1's l1tex 82%).

#define THREADS       256
#define F4_PER_THREAD 4
#define TILE_F4       (THREADS * F4_PER_THREAD)   // 1024 float4 = 16 KB

__global__ __launch_bounds__(THREADS)
void gather_wt_bulk(const int* __restrict__ rel_pos,
                    const float* __restrict__ W,       // [12,64]
                    float4* __restrict__ out4)
{
    __shared__ __align__(16)  float4 table4[64 * 3];   // table4[cls*3+c]
    __shared__ __align__(128) float4 stage4[TILE_F4];  // 16 KB staging

    float* table = reinterpret_cast<float*>(table4);
    unsigned t = threadIdx.x;

    // Build transposed table: table[c*12 + h] = W[h*64 + c]
    #pragma unroll
    for (int i = 0; i < 3; i++) {
        unsigned j = t + i * 256u;           // [0,768)
        unsigned h = j >> 6;
        unsigned c = j & 63u;
        table[c * 12u + h] = W[j];
    }
    __syncthreads();

    unsigned base = blockIdx.x * (unsigned)TILE_F4;

    // Gather: linear STS (conflict-free), random-row LDS from table.
    #pragma unroll
    for (int k = 0; k < F4_PER_THREAD; k++) {
        unsigned j = base + t + k * 256u;    // output float4 index
        unsigned e = j / 3u;                 // element
        unsigned c = j - e * 3u;             // chunk 0..2
        int cls = rel_pos[e];                // adjacent lanes merge in L1
        stage4[t + k * 256u] = table4[(unsigned)cls * 3u + c];
    }
    __syncthreads();

    // Bulk async store: 16 KB smem -> gmem, one instruction, no LSU per element.
    if (t == 0) {
        unsigned saddr;
        asm volatile("{ .reg .u64 a; cvta.to.shared.u64 a, %1; cvt.u32.u64 %0, a; }"
                     : "=r"(saddr) : "l"(stage4));
        unsigned long long gaddr = (unsigned long long)(out4 + base);
        asm volatile("fence.proxy.async;" ::: "memory");
        asm volatile("cp.async.bulk.global.shared::cta.bulk_group [%0], [%1], %2;"
                     :: "l"(gaddr), "r"(saddr), "n"(TILE_F4 * 16) : "memory");
        asm volatile("cp.async.bulk.commit_group;" ::: "memory");
        asm volatile("cp.async.bulk.wait_group 0;"  ::: "memory");
    }
}

// Fallback for any tail (not expected for these shapes): direct gather+store.
__global__ __launch_bounds__(THREADS)
void gather_wt_tail(const int* __restrict__ rel_pos,
                    const float* __restrict__ W,
                    float4* __restrict__ out4,
                    unsigned start, unsigned n4)
{
    __shared__ float4 table4[64 * 3];
    float* table = reinterpret_cast<float*>(table4);
    unsigned t = threadIdx.x;
    #pragma unroll
    for (int i = 0; i < 3; i++) {
        unsigned j = t + i * 256u;
        table[(j & 63u) * 12u + (j >> 6)] = W[j];
    }
    __syncthreads();

    unsigned j = start + blockIdx.x * (unsigned)THREADS + t;
    if (j < n4) {
        unsigned e = j / 3u;
        unsigned c = j - e * 3u;
        int cls = rel_pos[e];
        out4[j] = table4[(unsigned)cls * 3u + c];
    }
}

extern "C" void kernel_launch(void* const* d_in, const int* in_sizes, int n_in,
                              void* d_out, int out_size)
{
    const int*   rel_pos = (const int*)d_in[0];    // [4,2048,2048] int32
    // d_in[1] = hidden_states (unused; dtype carrier only)
    const float* W       = (const float*)d_in[2];  // [12,64] float32
    float4*      out4    = (float4*)d_out;

    unsigned n_elem = (unsigned)in_sizes[0];       // 16,777,216
    unsigned n4     = n_elem * 3u;                 // 50,331,648 float4
    unsigned blocks = n4 / (unsigned)TILE_F4;      // 49,152 (exact)
    unsigned done   = blocks * (unsigned)TILE_F4;

    if (blocks)
        gather_wt_bulk<<<blocks, THREADS>>>(rel_pos, W, out4);

    if (done < n4) {
        unsigned rem = n4 - done;
        unsigned tb  = (rem + THREADS - 1) / THREADS;
        gather_wt_tail<<<tb, THREADS>>>(rel_pos, W, out4, done, n4);
    }
}

// round 3
// speedup vs baseline: 1.4379x; 1.0047x over previous
#include <cuda_runtime.h>
#include <cuda_bf16.h>
#include <cstdint>

// out[e*12 + 0..11] = W[h][rel_pos[e]]  -> gather of W^T rows.
// R3: 4 tiles per CTA, double-buffered smem staging + cp.async.bulk stores so
// the TMA drain overlaps the next tile's gather (R2 exposed wait_group 0 per tile).

#define THREADS       256
#define F4_PER_THREAD 4
#define TILE_F4       (THREADS * F4_PER_THREAD)   // 1024 float4 = 16 KB
#define TILES_PER_CTA 4

__device__ __forceinline__ unsigned smem_u32(const void* p) {
    unsigned a;
    asm("{ .reg .u64 x; cvta.to.shared.u64 x, %1; cvt.u32.u64 %0, x; }"
        : "=r"(a) : "l"(p));
    return a;
}

__global__ __launch_bounds__(THREADS)
void gather_wt_pipe(const int* __restrict__ rel_pos,
                    const float* __restrict__ W,       // [12,64]
                    float4* __restrict__ out4)
{
    __shared__ __align__(16)  float4 table4[64 * 3];        // table4[cls*3+c]
    __shared__ __align__(128) float4 stage4[2][TILE_F4];    // 2 x 16 KB

    float* table = reinterpret_cast<float*>(table4);
    unsigned t = threadIdx.x;

    // Transposed table: table[c*12 + h] = W[h*64 + c]
    #pragma unroll
    for (int i = 0; i < 3; i++) {
        unsigned j = t + i * 256u;           // [0,768)
        table[(j & 63u) * 12u + (j >> 6)] = W[j];
    }
    __syncthreads();

    unsigned tile0 = blockIdx.x * (unsigned)TILES_PER_CTA;

    #pragma unroll
    for (int it = 0; it < TILES_PER_CTA; it++) {
        int buf = it & 1;
        unsigned base = (tile0 + (unsigned)it) * (unsigned)TILE_F4;

        // Before reusing a buffer, make sure its previous bulk store drained.
        if (it >= 2) {
            if (t == 0)
                asm volatile("cp.async.bulk.wait_group 1;" ::: "memory");
            __syncthreads();
        }

        // Gather: linear STS (conflict-free); random-row LDS from table.
        #pragma unroll
        for (int k = 0; k < F4_PER_THREAD; k++) {
            unsigned j = base + t + k * 256u;    // output float4 index
            unsigned e = j / 3u;                 // element
            unsigned c = j - e * 3u;             // chunk 0..2
            int cls = rel_pos[e];                // adjacent lanes merge in L1
            stage4[buf][t + k * 256u] = table4[(unsigned)cls * 3u + c];
        }
        __syncthreads();

        // Async bulk store: 16 KB smem -> gmem.
        if (t == 0) {
            unsigned saddr = smem_u32(stage4[buf]);
            unsigned long long gaddr = (unsigned long long)(out4 + base);
            asm volatile("fence.proxy.async;" ::: "memory");
            asm volatile("cp.async.bulk.global.shared::cta.bulk_group [%0], [%1], %2;"
                         :: "l"(gaddr), "r"(saddr), "n"(TILE_F4 * 16) : "memory");
            asm volatile("cp.async.bulk.commit_group;" ::: "memory");
        }
        // No sync needed here: only t==0 interacts with the bulk-store pipe,
        // and the buffer is not touched again until the wait above.
    }

    // Drain all outstanding stores before CTA exit (smem reuse by next CTA).
    if (t == 0)
        asm volatile("cp.async.bulk.wait_group 0;" ::: "memory");
    __syncthreads();
}

// Generic tail (unused for the benchmark shapes): direct gather + store.
__global__ __launch_bounds__(THREADS)
void gather_wt_tail(const int* __restrict__ rel_pos,
                    const float* __restrict__ W,
                    float4* __restrict__ out4,
                    unsigned start, unsigned n4)
{
    __shared__ float4 table4[64 * 3];
    float* table = reinterpret_cast<float*>(table4);
    unsigned t = threadIdx.x;
    #pragma unroll
    for (int i = 0; i < 3; i++) {
        unsigned j = t + i * 256u;
        table[(j & 63u) * 12u + (j >> 6)] = W[j];
    }
    __syncthreads();

    unsigned j = start + blockIdx.x * (unsigned)THREADS + t;
    if (j < n4) {
        unsigned e = j / 3u;
        unsigned c = j - e * 3u;
        int cls = rel_pos[e];
        out4[j] = table4[(unsigned)cls * 3u + c];
    }
}

extern "C" void kernel_launch(void* const* d_in, const int* in_sizes, int n_in,
                              void* d_out, int out_size)
{
    const int*   rel_pos = (const int*)d_in[0];    // [4,2048,2048] int32
    // d_in[1] = hidden_states (unused; dtype carrier only)
    const float* W       = (const float*)d_in[2];  // [12,64] float32
    float4*      out4    = (float4*)d_out;

    unsigned n_elem = (unsigned)in_sizes[0];       // 16,777,216
    unsigned n4     = n_elem * 3u;                 // 50,331,648 float4
    unsigned per_cta = (unsigned)(TILE_F4 * TILES_PER_CTA);   // 4096 float4
    unsigned blocks  = n4 / per_cta;               // 12,288 (exact for bench)
    unsigned done    = blocks * per_cta;

    if (blocks)
        gather_wt_pipe<<<blocks, THREADS>>>(rel_pos, W, out4);

    if (done < n4) {
        unsigned rem = n4 - done;
        unsigned tb  = (rem + THREADS - 1) / THREADS;
        gather_wt_tail<<<tb, THREADS>>>(rel_pos, W, out4, done, n4);
    }
}